// round 2
// baseline (speedup 1.0000x reference)
#include <cuda_runtime.h>
#include <stdint.h>

#define C 64
#define MAXN 100000

// Scratch for y = x @ W_neigh^T (device global: no allocs allowed in kernel_launch)
__device__ float g_ybuf[(size_t)MAXN * C];

// ---------------------------------------------------------------------------
// Kernel 1: per-node fused dual GEMM.
//   out[n][:]  = x[n][:] @ Ws^T + (bs + bn)
//   ybuf[n][:] = x[n][:] @ Wn^T
// One thread per node; x row cached in 64 registers; W tiles staged in shared
// (all lanes read the same W address per step -> broadcast LDS, conflict-free).
// ---------------------------------------------------------------------------
__global__ void __launch_bounds__(128)
fused_gemm_kernel(const float* __restrict__ x,
                  const float* __restrict__ Ws,
                  const float* __restrict__ bs,
                  const float* __restrict__ Wn,
                  const float* __restrict__ bn,
                  float* __restrict__ out,
                  int N) {
    __shared__ float sWs[C * C];
    __shared__ float sWn[C * C];
    __shared__ float sb[C];

    int tid = threadIdx.x;
    for (int i = tid; i < C * C; i += blockDim.x) {
        sWs[i] = Ws[i];
        sWn[i] = Wn[i];
    }
    if (tid < C) sb[tid] = bs[tid] + bn[tid];
    __syncthreads();

    int n = blockIdx.x * blockDim.x + tid;
    if (n >= N) return;

    // Load full x row into registers (16 x float4 = 64 floats)
    float4 xr[16];
    const float4* xp = reinterpret_cast<const float4*>(x + (size_t)n * C);
#pragma unroll
    for (int i = 0; i < 16; i++) xr[i] = xp[i];

    float4* op = reinterpret_cast<float4*>(out + (size_t)n * C);
    float4* yp = reinterpret_cast<float4*>(g_ybuf + (size_t)n * C);

    // Process 4 output columns at a time; keep outer loop rolled so the
    // inner body stays inside L0/L1.5 I$.
#pragma unroll 1
    for (int jg = 0; jg < C; jg += 4) {
        float accs[4], accn[4];
#pragma unroll
        for (int jj = 0; jj < 4; jj++) {
            accs[jj] = sb[jg + jj];
            accn[jj] = 0.0f;
        }
#pragma unroll
        for (int k = 0; k < 16; k++) {
            float4 xv = xr[k];
#pragma unroll
            for (int jj = 0; jj < 4; jj++) {
                float4 w = *reinterpret_cast<const float4*>(&sWs[(jg + jj) * C + k * 4]);
                accs[jj] = fmaf(xv.x, w.x, accs[jj]);
                accs[jj] = fmaf(xv.y, w.y, accs[jj]);
                accs[jj] = fmaf(xv.z, w.z, accs[jj]);
                accs[jj] = fmaf(xv.w, w.w, accs[jj]);
                float4 u = *reinterpret_cast<const float4*>(&sWn[(jg + jj) * C + k * 4]);
                accn[jj] = fmaf(xv.x, u.x, accn[jj]);
                accn[jj] = fmaf(xv.y, u.y, accn[jj]);
                accn[jj] = fmaf(xv.z, u.z, accn[jj]);
                accn[jj] = fmaf(xv.w, u.w, accn[jj]);
            }
        }
        op[jg >> 2] = make_float4(accs[0], accs[1], accs[2], accs[3]);
        yp[jg >> 2] = make_float4(accn[0], accn[1], accn[2], accn[3]);
    }
}

// ---------------------------------------------------------------------------
// Kernel 2: edge scatter. 16 lanes per edge; lane i handles float4 chunk i.
//   out[row][:] += edge_weight * ybuf[col][:]
// NOTE: edge_index is int32 on device (JAX x64 disabled downcasts int64).
// Gather is a coalesced 256B row read (L2-resident); scatter uses vectorized
// red.global.add.v4.f32 (sm_90+) -> 4x fewer atomic ops than scalar atomicAdd.
// ---------------------------------------------------------------------------
__global__ void __launch_bounds__(256)
scatter_kernel(const int* __restrict__ ei,
               const float* __restrict__ ew,
               float* __restrict__ out,
               int E) {
    long long t = (long long)blockIdx.x * blockDim.x + threadIdx.x;
    int e = (int)(t >> 4);
    if (e >= E) return;
    int lane = (int)t & 15;

    int dst = __ldg(ei + e);              // row (destination)
    int src = __ldg(ei + (size_t)E + e);  // col (source)
    float w = __ldg(ew + e);

    float4 v = __ldg(reinterpret_cast<const float4*>(g_ybuf + (size_t)src * C) + lane);
    float4 r;
    r.x = v.x * w;
    r.y = v.y * w;
    r.z = v.z * w;
    r.w = v.w * w;

    float* op = out + (size_t)dst * C + (lane << 2);
    asm volatile("red.global.add.v4.f32 [%0], {%1, %2, %3, %4};"
                 :: "l"(op), "f"(r.x), "f"(r.y), "f"(r.z), "f"(r.w)
                 : "memory");
}

// ---------------------------------------------------------------------------
// Inputs (metadata order): x[N*64] f32, edge_index[2*E] i32, edge_weight[E] f32,
// W_self[64*64] f32, b_self[64] f32, W_neigh[64*64] f32, b_neigh[64] f32,
// num_nodes (scalar, unused -- N derived from in_sizes[0]).
// Output: float32 [N*64].
// ---------------------------------------------------------------------------
extern "C" void kernel_launch(void* const* d_in, const int* in_sizes, int n_in,
                              void* d_out, int out_size) {
    const float* x  = (const float*)d_in[0];
    const int*   ei = (const int*)d_in[1];
    const float* ew = (const float*)d_in[2];
    const float* Ws = (const float*)d_in[3];
    const float* bs = (const float*)d_in[4];
    const float* Wn = (const float*)d_in[5];
    const float* bn = (const float*)d_in[6];
    float* out = (float*)d_out;

    int N = in_sizes[0] / C;
    int E = in_sizes[2];

    // 1) out = x@Ws^T + (bs+bn);  ybuf = x@Wn^T
    fused_gemm_kernel<<<(N + 127) / 128, 128>>>(x, Ws, bs, Wn, bn, out, N);

    // 2) out[row] += w * ybuf[col]   (vector atomics)
    long long total = (long long)E * 16;
    int blocks = (int)((total + 255) / 256);
    scatter_kernel<<<blocks, 256>>>(ei, ew, out, E);
}